// round 1
// baseline (speedup 1.0000x reference)
#include <cuda_runtime.h>
#include <cstdint>

#define NN  100000
#define RR  3
#define EE  320000
#define HH  4
#define HD_ 128

// ---------------- scratch (device globals; no allocs allowed) ----------------
__device__ float    g_hs  [(size_t)RR * NN * HD_];   // hs per relation  [r][n][128]
__device__ float    g_rst [(size_t)RR * NN * HD_];   // unnormalized agg -> z_r in place
__device__ float    g_el  [RR * NN * HH];
__device__ float    g_er  [RR * NN * HH];
__device__ unsigned g_m   [RR * NN * HH];            // encoded segment max
__device__ float    g_ssum[RR * NN * HH];
__device__ float    g_A   [RR * 128 * 128];          // Wt_src[r] @ Wg[r]
__device__ float    g_csrc[RR * 128];                // bt_src[r] @ Wg[r]
__device__ float    g_erw [RR * 128 * HH];           // combined er weights [r][f][h]
__device__ float    g_erb [RR * HH];
__device__ float    g_wsum[RR];
__device__ float    g_aw  [RR];

// monotone float<->uint encoding for atomicMax over floats (any sign)
__device__ __forceinline__ unsigned fenc(float f) {
    unsigned u = __float_as_uint(f);
    return (u & 0x80000000u) ? ~u : (u | 0x80000000u);
}
__device__ __forceinline__ float fdec(unsigned u) {
    unsigned v = (u & 0x80000000u) ? (u & 0x7fffffffu) : ~u;
    return __uint_as_float(v);
}

__device__ __forceinline__ void red4(float* p, float a, float b, float c, float d) {
    asm volatile("red.global.add.v4.f32 [%0], {%1, %2, %3, %4};"
                 :: "l"(p), "f"(a), "f"(b), "f"(c), "f"(d) : "memory");
}

// ---------------- weight combination ----------------
// A[r][f][j] = sum_i Wt_src[r][f][i] * Wg[r][i][j];  c_src[r][j] = sum_i bt_src[r][i]*Wg[r][i][j]
__global__ void k_combine_src(const float* __restrict__ Wt_src,
                              const float* __restrict__ bt_src,
                              const float* __restrict__ Wg) {
    int r = blockIdx.y, f = blockIdx.x, j = threadIdx.x;
    __shared__ float wt[128];
    wt[j] = Wt_src[(r * 128 + f) * 128 + j];
    __syncthreads();
    const float* wg = Wg + r * 128 * 128;
    float acc = 0.f;
#pragma unroll 8
    for (int i = 0; i < 128; i++) acc += wt[i] * wg[i * 128 + j];
    g_A[(r * 128 + f) * 128 + j] = acc;
    if (f == 0) {
        float c = 0.f;
        for (int i = 0; i < 128; i++) c += bt_src[r * 128 + i] * wg[i * 128 + j];
        g_csrc[r * 128 + j] = c;
    }
}

// er_w[r][f][h] = sum_i Wt_dst[f][i] * P[i][h],  P[i][h] = sum_d Wg[r][i][h*32+d]*attn_r[r][h][d]
__global__ void k_combine_dst(const float* __restrict__ Wt_dst,
                              const float* __restrict__ bt_dst,
                              const float* __restrict__ Wg,
                              const float* __restrict__ attn_r) {
    int r = blockIdx.x, t = threadIdx.x;  // 128 threads
    __shared__ float P[128][4];
    const float* wg = Wg + r * 128 * 128;
    const float* ar = attn_r + r * 128;
    for (int h = 0; h < 4; h++) {
        float s = 0.f;
        for (int d = 0; d < 32; d++) s += wg[t * 128 + h * 32 + d] * ar[h * 32 + d];
        P[t][h] = s;
    }
    __syncthreads();
    float s[4] = {0.f, 0.f, 0.f, 0.f};
    for (int i = 0; i < 128; i++) {
        float w = Wt_dst[t * 128 + i];
        for (int h = 0; h < 4; h++) s[h] += w * P[i][h];
    }
    for (int h = 0; h < 4; h++) g_erw[(r * 128 + t) * 4 + h] = s[h];
    if (t < 4) {
        float b = 0.f;
        for (int i = 0; i < 128; i++) b += bt_dst[i] * P[i][t];
        g_erb[r * 4 + t] = b;
    }
}

// er[r][n][h] = dst_feat[n] . er_w[r][:,h] + er_b[r][h]
__global__ void k_er(const float* __restrict__ dst_feat) {
    __shared__ float sw[RR * 128 * 4];
    __shared__ float sb[RR * 4];
    int t = threadIdx.x;
    for (int idx = t; idx < RR * 128 * 4; idx += blockDim.x) sw[idx] = g_erw[idx];
    if (t < RR * 4) sb[t] = g_erb[t];
    __syncthreads();
    int n = blockIdx.x * blockDim.x + t;
    if (n >= NN) return;
    float acc[RR * 4];
    for (int q = 0; q < RR * 4; q++) acc[q] = sb[q];
    const float4* row = (const float4*)(dst_feat + (size_t)n * 128);
#pragma unroll 4
    for (int f4 = 0; f4 < 32; f4++) {
        float4 v = row[f4];
        const float c[4] = {v.x, v.y, v.z, v.w};
        for (int cc = 0; cc < 4; cc++) {
            int f = f4 * 4 + cc;
            for (int r = 0; r < RR; r++)
                for (int h = 0; h < 4; h++)
                    acc[r * 4 + h] += c[cc] * sw[(r * 128 + f) * 4 + h];
        }
    }
    for (int r = 0; r < RR; r++)
        for (int h = 0; h < 4; h++)
            g_er[(r * NN + n) * 4 + h] = acc[r * 4 + h];
}

// ---------------- hs GEMM: [N,128] @ [128,128] + bias, fused el epilogue ----------------
__global__ __launch_bounds__(256) void k_hs(const float* __restrict__ src_feats,
                                            const float* __restrict__ attn_l) {
    int r = blockIdx.y;
    int row0 = blockIdx.x * 32;
    __shared__ float Wsh[64][128];
    __shared__ float Ash[32][68];
    __shared__ float elbuf[32][4][8];
    __shared__ float alsh[128];
    __shared__ float csh[128];
    int t = threadIdx.x;
    if (t < 128) { alsh[t] = attn_l[r * 128 + t]; csh[t] = g_csrc[r * 128 + t]; }
    const float* A = g_A + r * 128 * 128;
    const float* X = src_feats + (size_t)r * NN * 128;
    float acc[4][4];
    for (int i = 0; i < 4; i++) for (int c = 0; c < 4; c++) acc[i][c] = 0.f;
    int rg = t >> 5, cg = t & 31;
    int colb = cg * 4;
    for (int kc = 0; kc < 128; kc += 64) {
        __syncthreads();
        for (int idx = t; idx < 64 * 128; idx += 256) {
            int kk = idx >> 7, j = idx & 127;
            Wsh[kk][j] = A[(kc + kk) * 128 + j];
        }
        for (int idx = t; idx < 32 * 64; idx += 256) {
            int rr = idx >> 6, cc = idx & 63;
            Ash[rr][cc] = X[(size_t)(row0 + rr) * 128 + kc + cc];
        }
        __syncthreads();
#pragma unroll 4
        for (int kk = 0; kk < 64; kk++) {
            float4 b = *(const float4*)&Wsh[kk][colb];
            float a0 = Ash[rg * 4 + 0][kk];
            float a1 = Ash[rg * 4 + 1][kk];
            float a2 = Ash[rg * 4 + 2][kk];
            float a3 = Ash[rg * 4 + 3][kk];
            acc[0][0] += a0 * b.x; acc[0][1] += a0 * b.y; acc[0][2] += a0 * b.z; acc[0][3] += a0 * b.w;
            acc[1][0] += a1 * b.x; acc[1][1] += a1 * b.y; acc[1][2] += a1 * b.z; acc[1][3] += a1 * b.w;
            acc[2][0] += a2 * b.x; acc[2][1] += a2 * b.y; acc[2][2] += a2 * b.z; acc[2][3] += a2 * b.w;
            acc[3][0] += a3 * b.x; acc[3][1] += a3 * b.y; acc[3][2] += a3 * b.z; acc[3][3] += a3 * b.w;
        }
    }
    float* hsout = g_hs + ((size_t)r * NN + row0) * 128;
#pragma unroll
    for (int i = 0; i < 4; i++) {
        int row = rg * 4 + i;
        float4 v;
        v.x = acc[i][0] + csh[colb + 0];
        v.y = acc[i][1] + csh[colb + 1];
        v.z = acc[i][2] + csh[colb + 2];
        v.w = acc[i][3] + csh[colb + 3];
        float elp = v.x * alsh[colb] + v.y * alsh[colb + 1] + v.z * alsh[colb + 2] + v.w * alsh[colb + 3];
        *(float4*)(hsout + (size_t)row * 128 + colb) = v;
        elbuf[row][cg >> 3][cg & 7] = elp;
    }
    __syncthreads();
    if (t < 128) {
        int row = t >> 2, h = t & 3;
        float s = 0.f;
        for (int q = 0; q < 8; q++) s += elbuf[row][h][q];
        g_el[((size_t)r * NN + row0 + row) * 4 + h] = s;
    }
}

// ---------------- edge pass 1: segment max ----------------
__global__ void k_edge1(const int* __restrict__ src_idx, const int* __restrict__ dst_idx) {
    int r = blockIdx.y;
    int t = blockIdx.x * blockDim.x + threadIdx.x;
    if (t >= EE * 4) return;
    int e = t >> 2, h = t & 3;
    int s = src_idx[r * EE + e];
    int d = dst_idx[r * EE + e];
    float v = g_el[(r * NN + s) * 4 + h] + g_er[(r * NN + d) * 4 + h];
    v = v > 0.f ? v : 0.2f * v;
    atomicMax(&g_m[(r * NN + d) * 4 + h], fenc(v));
}

// ---------------- edge pass 2: exp, segment sum, weighted aggregation ----------------
__global__ void k_edge2(const int* __restrict__ src_idx, const int* __restrict__ dst_idx) {
    int r = blockIdx.y;
    int t = blockIdx.x * blockDim.x + threadIdx.x;
    if (t >= EE * 4) return;
    int e = t >> 2, h = t & 3;
    int s = src_idx[r * EE + e];
    int d = dst_idx[r * EE + e];
    float v = g_el[(r * NN + s) * 4 + h] + g_er[(r * NN + d) * 4 + h];
    v = v > 0.f ? v : 0.2f * v;
    float m = fdec(g_m[(r * NN + d) * 4 + h]);
    float ex = __expf(v - m);
    atomicAdd(&g_ssum[(r * NN + d) * 4 + h], ex);
    const float4* hp = (const float4*)(g_hs + ((size_t)r * NN + s) * 128 + h * 32);
    float* rp = g_rst + ((size_t)r * NN + d) * 128 + h * 32;
#pragma unroll
    for (int q = 0; q < 8; q++) {
        float4 x = hp[q];
        red4(rp + q * 4, ex * x.x, ex * x.y, ex * x.z, ex * x.w);
    }
}

// ---------------- normalize + bias + ELU (z_r in place in g_rst) ----------------
__global__ void k_fin(const float* __restrict__ bias_g) {
    int rn = blockIdx.x * blockDim.x + threadIdx.x;
    if (rn >= RR * NN) return;
    int r = rn / NN;
    float inv[4];
    for (int h = 0; h < 4; h++) inv[h] = 1.f / (g_ssum[rn * 4 + h] + 1e-9f);
    float4* z = (float4*)(g_rst + (size_t)rn * 128);
    const float* bg = bias_g + r * 128;
#pragma unroll 8
    for (int q = 0; q < 32; q++) {
        float4 v = z[q];
        int col = q * 4;
        float iv = inv[col >> 5];
        v.x = v.x * iv + bg[col + 0];
        v.y = v.y * iv + bg[col + 1];
        v.z = v.z * iv + bg[col + 2];
        v.w = v.w * iv + bg[col + 3];
        v.x = v.x > 0.f ? v.x : expm1f(v.x);
        v.y = v.y > 0.f ? v.y : expm1f(v.y);
        v.z = v.z > 0.f ? v.z : expm1f(v.z);
        v.w = v.w > 0.f ? v.w : expm1f(v.w);
        z[q] = v;
    }
}

// ---------------- semantic attention GEMM: w-sum per relation ----------------
__global__ __launch_bounds__(256) void k_sem(const float* __restrict__ W1,
                                             const float* __restrict__ b1,
                                             const float* __restrict__ W2) {
    int row0 = blockIdx.x * 32;  // rows over flattened [R*N]
    __shared__ float Wsh[64][128];
    __shared__ float Ash[32][68];
    __shared__ float b1sh[128];
    __shared__ float w2sh[128];
    __shared__ float wsums[8];
    int t = threadIdx.x;
    if (t < 128) { b1sh[t] = b1[t]; w2sh[t] = W2[t]; }
    float acc[4][4];
    for (int i = 0; i < 4; i++) for (int c = 0; c < 4; c++) acc[i][c] = 0.f;
    int rg = t >> 5, cg = t & 31;
    int colb = cg * 4;
    for (int kc = 0; kc < 128; kc += 64) {
        __syncthreads();
        for (int idx = t; idx < 64 * 128; idx += 256) {
            int kk = idx >> 7, j = idx & 127;
            Wsh[kk][j] = W1[(kc + kk) * 128 + j];
        }
        for (int idx = t; idx < 32 * 64; idx += 256) {
            int rr = idx >> 6, cc = idx & 63;
            Ash[rr][cc] = g_rst[(size_t)(row0 + rr) * 128 + kc + cc];
        }
        __syncthreads();
#pragma unroll 4
        for (int kk = 0; kk < 64; kk++) {
            float4 b = *(const float4*)&Wsh[kk][colb];
            float a0 = Ash[rg * 4 + 0][kk];
            float a1 = Ash[rg * 4 + 1][kk];
            float a2 = Ash[rg * 4 + 2][kk];
            float a3 = Ash[rg * 4 + 3][kk];
            acc[0][0] += a0 * b.x; acc[0][1] += a0 * b.y; acc[0][2] += a0 * b.z; acc[0][3] += a0 * b.w;
            acc[1][0] += a1 * b.x; acc[1][1] += a1 * b.y; acc[1][2] += a1 * b.z; acc[1][3] += a1 * b.w;
            acc[2][0] += a2 * b.x; acc[2][1] += a2 * b.y; acc[2][2] += a2 * b.z; acc[2][3] += a2 * b.w;
            acc[3][0] += a3 * b.x; acc[3][1] += a3 * b.y; acc[3][2] += a3 * b.z; acc[3][3] += a3 * b.w;
        }
    }
    float tot = 0.f;
#pragma unroll
    for (int i = 0; i < 4; i++) {
        float p = 0.f;
        for (int c = 0; c < 4; c++)
            p += w2sh[colb + c] * tanhf(acc[i][c] + b1sh[colb + c]);
        tot += p;
    }
    for (int off = 16; off; off >>= 1) tot += __shfl_down_sync(0xffffffffu, tot, off);
    if (cg == 0) wsums[rg] = tot;
    __syncthreads();
    if (t == 0) {
        float s = 0.f;
        for (int q = 0; q < 8; q++) s += wsums[q];
        int r = row0 / NN;
        atomicAdd(&g_wsum[r], s);
    }
}

// ---------------- softmax over relations ----------------
__global__ void k_soft(float* __restrict__ out, int out_size) {
    if (threadIdx.x == 0) {
        float w[RR];
        float m = -1e30f;
        for (int r = 0; r < RR; r++) { w[r] = g_wsum[r] / (float)NN; m = fmaxf(m, w[r]); }
        float s = 0.f;
        for (int r = 0; r < RR; r++) { w[r] = expf(w[r] - m); s += w[r]; }
        for (int r = 0; r < RR; r++) {
            float a = w[r] / s;
            g_aw[r] = a;
            out[out_size - RR + r] = a;
        }
    }
}

// ---------------- final weighted combination ----------------
__global__ void k_out(float* __restrict__ out) {
    int t = blockIdx.x * blockDim.x + threadIdx.x;
    if (t >= NN * 32) return;
    float a0 = g_aw[0], a1 = g_aw[1], a2 = g_aw[2];
    const float4* z0 = (const float4*)g_rst + t;
    const float4* z1 = z0 + (size_t)NN * 32;
    const float4* z2 = z1 + (size_t)NN * 32;
    float4 x = *z0, y = *z1, z = *z2;
    float4 o;
    o.x = a0 * x.x + a1 * y.x + a2 * z.x;
    o.y = a0 * x.y + a1 * y.y + a2 * z.y;
    o.z = a0 * x.z + a1 * y.z + a2 * z.z;
    o.w = a0 * x.w + a1 * y.w + a2 * z.w;
    ((float4*)out)[t] = o;
}

// ---------------- launch ----------------
extern "C" void kernel_launch(void* const* d_in, const int* in_sizes, int n_in,
                              void* d_out, int out_size) {
    const float* dst_feat  = (const float*)d_in[0];
    const float* src_feats = (const float*)d_in[1];
    const int*   src_idx   = (const int*)d_in[2];
    const int*   dst_idx   = (const int*)d_in[3];
    const float* Wt_dst    = (const float*)d_in[4];
    const float* bt_dst    = (const float*)d_in[5];
    const float* Wt_src    = (const float*)d_in[6];
    const float* bt_src    = (const float*)d_in[7];
    const float* Wg        = (const float*)d_in[8];
    const float* attn_l    = (const float*)d_in[9];
    const float* attn_r    = (const float*)d_in[10];
    const float* bias_g    = (const float*)d_in[11];
    const float* W1        = (const float*)d_in[12];
    const float* b1        = (const float*)d_in[13];
    const float* W2        = (const float*)d_in[14];
    float* out = (float*)d_out;

    void *pm, *ps, *pr, *pw;
    cudaGetSymbolAddress(&pm, g_m);
    cudaGetSymbolAddress(&ps, g_ssum);
    cudaGetSymbolAddress(&pr, g_rst);
    cudaGetSymbolAddress(&pw, g_wsum);
    cudaMemsetAsync(pm, 0, (size_t)RR * NN * HH * 4, 0);
    cudaMemsetAsync(ps, 0, (size_t)RR * NN * HH * 4, 0);
    cudaMemsetAsync(pr, 0, (size_t)RR * NN * HD_ * 4, 0);
    cudaMemsetAsync(pw, 0, RR * 4, 0);

    k_combine_src<<<dim3(128, RR), 128>>>(Wt_src, bt_src, Wg);
    k_combine_dst<<<RR, 128>>>(Wt_dst, bt_dst, Wg, attn_r);
    k_er<<<(NN + 127) / 128, 128>>>(dst_feat);
    k_hs<<<dim3(NN / 32, RR), 256>>>(src_feats, attn_l);
    k_edge1<<<dim3((EE * 4 + 255) / 256, RR), 256>>>(src_idx, dst_idx);
    k_edge2<<<dim3((EE * 4 + 255) / 256, RR), 256>>>(src_idx, dst_idx);
    k_fin<<<(RR * NN + 255) / 256, 256>>>(bias_g);
    k_sem<<<(RR * NN) / 32, 256>>>(W1, b1, W2);
    k_soft<<<1, 32>>>(out, out_size);
    k_out<<<(NN * 32 + 255) / 256, 256>>>(out);
}